// round 2
// baseline (speedup 1.0000x reference)
#include <cuda_runtime.h>
#include <cstdint>

#define MAX_LEVEL 12
#define FEAT_LEVELS 3
#define FEAT_DIM 8
#define TABLE 1048577

__global__ __launch_bounds__(256) void feature_octree_kernel(
    const float* __restrict__ coord,      // (N, 3)
    const float* __restrict__ features,   // (3, TABLE, 8)
    const int*   __restrict__ indices,    // (3, N, 8)
    float*       __restrict__ out,        // (N, 8)
    int n)
{
    int t = blockIdx.x * blockDim.x + threadIdx.x;
    if (t >= n) return;

    float x = coord[3 * t + 0];
    float y = coord[3 * t + 1];
    float z = coord[3 * t + 2];

    float acc0 = 0.f, acc1 = 0.f, acc2 = 0.f, acc3 = 0.f;
    float acc4 = 0.f, acc5 = 0.f, acc6 = 0.f, acc7 = 0.f;

    #pragma unroll
    for (int i = 0; i < FEAT_LEVELS; i++) {
        const int level = MAX_LEVEL - i;
        const float scale = (float)(1 << level);

        // coords = 2^level * (x*0.5 + 0.5); d = frac(coords); smoothstep
        float cx = scale * (x * 0.5f + 0.5f);
        float cy = scale * (y * 0.5f + 0.5f);
        float cz = scale * (z * 0.5f + 0.5f);
        float dx = cx - floorf(cx);
        float dy = cy - floorf(cy);
        float dz = cz - floorf(cz);
        dx = 3.0f * dx * dx - 2.0f * dx * dx * dx;
        dy = 3.0f * dy * dy - 2.0f * dy * dy * dy;
        dz = 3.0f * dz * dz - 2.0f * dz * dz * dz;

        const float wx1 = dx, wx0 = 1.0f - dx;
        const float wy1 = dy, wy0 = 1.0f - dy;
        const float wz1 = dz, wz0 = 1.0f - dz;

        // index row: 8 ints, 32B-aligned
        const int* idx_row = indices + ((size_t)i * n + (size_t)t) * 8;
        const int4 ia = __ldg((const int4*)idx_row);
        const int4 ib = __ldg((const int4*)(idx_row + 4));
        const int id[8] = {ia.x, ia.y, ia.z, ia.w, ib.x, ib.y, ib.z, ib.w};

        // 8 weights: bit2 -> x, bit1 -> y, bit0 -> z.
        // Sentinel row (TABLE-1) is defined as zero in the reference: zero the
        // weight instead of masking the load (branchless select).
        float w[8];
        w[0] = wx0 * wy0 * wz0;
        w[1] = wx0 * wy0 * wz1;
        w[2] = wx0 * wy1 * wz0;
        w[3] = wx0 * wy1 * wz1;
        w[4] = wx1 * wy0 * wz0;
        w[5] = wx1 * wy0 * wz1;
        w[6] = wx1 * wy1 * wz0;
        w[7] = wx1 * wy1 * wz1;
        #pragma unroll
        for (int k = 0; k < 8; k++)
            w[k] = (id[k] == TABLE - 1) ? 0.0f : w[k];

        const float* ftab = features + (size_t)(FEAT_LEVELS - 1 - i) * TABLE * FEAT_DIM;

        // issue all 16 vector gathers before consuming (max MLP)
        float4 g0[8], g1[8];
        #pragma unroll
        for (int k = 0; k < 8; k++) {
            const float4* row = (const float4*)(ftab + (size_t)id[k] * FEAT_DIM);
            g0[k] = __ldg(row);
            g1[k] = __ldg(row + 1);
        }

        #pragma unroll
        for (int k = 0; k < 8; k++) {
            const float wk = w[k];
            acc0 = fmaf(wk, g0[k].x, acc0);
            acc1 = fmaf(wk, g0[k].y, acc1);
            acc2 = fmaf(wk, g0[k].z, acc2);
            acc3 = fmaf(wk, g0[k].w, acc3);
            acc4 = fmaf(wk, g1[k].x, acc4);
            acc5 = fmaf(wk, g1[k].y, acc5);
            acc6 = fmaf(wk, g1[k].z, acc6);
            acc7 = fmaf(wk, g1[k].w, acc7);
        }
    }

    float4* o = (float4*)(out + (size_t)t * 8);
    o[0] = make_float4(acc0, acc1, acc2, acc3);
    o[1] = make_float4(acc4, acc5, acc6, acc7);
}

extern "C" void kernel_launch(void* const* d_in, const int* in_sizes, int n_in,
                              void* d_out, int out_size)
{
    const float* coord    = (const float*)d_in[0];
    const float* features = (const float*)d_in[1];
    const int*   indices  = (const int*)d_in[2];
    float*       out      = (float*)d_out;

    const int n = in_sizes[0] / 3;
    const int threads = 256;
    const int blocks = (n + threads - 1) / threads;
    feature_octree_kernel<<<blocks, threads>>>(coord, features, indices, out, n);
}

// round 6
// speedup vs baseline: 1.0214x; 1.0214x over previous
#include <cuda_runtime.h>
#include <cstdint>

#define MAX_LEVEL 12
#define FEAT_LEVELS 3
#define FEAT_DIM 8
#define TABLE 1048577

// Two lanes per point: lane pair (h=0,1) each owns one float4 half of every
// gathered 32B feature row. Both halves of a row are issued in the SAME
// instruction by adjacent lanes -> same 128B line -> ONE L1tex wavefront per
// row instead of two. This halves the L1tex wavefront count, which R2 ncu
// showed to be the binding resource (l1tex 73.9%, dram 51%, issue 7.6%).
__global__ __launch_bounds__(256) void feature_octree_pair_kernel(
    const float* __restrict__ coord,      // (N, 3)
    const float* __restrict__ features,   // (3, TABLE, 8)
    const int*   __restrict__ indices,    // (3, N, 8)
    float*       __restrict__ out,        // (N, 8)
    int n)
{
    const int t = blockIdx.x * blockDim.x + threadIdx.x;
    const int p = t >> 1;   // point index
    const int h = t & 1;    // which float4 half of each feature row
    if (p >= n) return;

    // coord: streaming, read once per pair (broadcast within instruction)
    const float x = __ldcs(coord + 3 * p + 0);
    const float y = __ldcs(coord + 3 * p + 1);
    const float z = __ldcs(coord + 3 * p + 2);

    float a0 = 0.f, a1 = 0.f, a2 = 0.f, a3 = 0.f;

    #pragma unroll
    for (int i = 0; i < FEAT_LEVELS; i++) {
        const int level = MAX_LEVEL - i;
        const float scale = (float)(1 << level);

        // coords = 2^level * (x*0.5 + 0.5); d = frac; smoothstep
        float cx = scale * (x * 0.5f + 0.5f);
        float cy = scale * (y * 0.5f + 0.5f);
        float cz = scale * (z * 0.5f + 0.5f);
        float dx = cx - floorf(cx);
        float dy = cy - floorf(cy);
        float dz = cz - floorf(cz);
        dx = 3.0f * dx * dx - 2.0f * dx * dx * dx;
        dy = 3.0f * dy * dy - 2.0f * dy * dy * dy;
        dz = 3.0f * dz * dz - 2.0f * dz * dz * dz;

        const float wx1 = dx, wx0 = 1.0f - dx;
        const float wy1 = dy, wy0 = 1.0f - dy;
        const float wz1 = dz, wz0 = 1.0f - dz;

        // index row: 8 ints, 32B-aligned; streaming (evict-first), both lanes
        // of a pair read identical addresses (broadcast).
        const int* idx_row = indices + ((size_t)i * n + (size_t)p) * 8;
        const int4 ia = __ldcs((const int4*)idx_row);
        const int4 ib = __ldcs((const int4*)(idx_row + 4));
        const int id[8] = {ia.x, ia.y, ia.z, ia.w, ib.x, ib.y, ib.z, ib.w};

        // 8 corner weights (bit2->x, bit1->y, bit0->z). Sentinel row
        // (TABLE-1) is zero in the reference: zero its weight (branchless).
        float w[8];
        w[0] = wx0 * wy0 * wz0;
        w[1] = wx0 * wy0 * wz1;
        w[2] = wx0 * wy1 * wz0;
        w[3] = wx0 * wy1 * wz1;
        w[4] = wx1 * wy0 * wz0;
        w[5] = wx1 * wy0 * wz1;
        w[6] = wx1 * wy1 * wz0;
        w[7] = wx1 * wy1 * wz1;
        #pragma unroll
        for (int k = 0; k < 8; k++)
            w[k] = (id[k] == TABLE - 1) ? 0.0f : w[k];

        const float4* ftab4 = (const float4*)
            (features + (size_t)(FEAT_LEVELS - 1 - i) * TABLE * FEAT_DIM);

        // Issue all 8 gathers for this level before consuming (MLP=8/thread,
        // 2x thread count keeps per-SM outstanding loads equal to R2).
        // Default cache policy so table lines persist in L2.
        float4 g[8];
        #pragma unroll
        for (int k = 0; k < 8; k++)
            g[k] = __ldg(ftab4 + (size_t)id[k] * 2 + h);

        #pragma unroll
        for (int k = 0; k < 8; k++) {
            a0 = fmaf(w[k], g[k].x, a0);
            a1 = fmaf(w[k], g[k].y, a1);
            a2 = fmaf(w[k], g[k].z, a2);
            a3 = fmaf(w[k], g[k].w, a3);
        }
    }

    // Adjacent lanes store adjacent float4s -> fully coalesced; streaming.
    __stcs((float4*)out + (size_t)p * 2 + h, make_float4(a0, a1, a2, a3));
}

extern "C" void kernel_launch(void* const* d_in, const int* in_sizes, int n_in,
                              void* d_out, int out_size)
{
    const float* coord    = (const float*)d_in[0];
    const float* features = (const float*)d_in[1];
    const int*   indices  = (const int*)d_in[2];
    float*       out      = (float*)d_out;

    const int n = in_sizes[0] / 3;
    const int threads = 256;
    const long long total = 2LL * n;
    const int blocks = (int)((total + threads - 1) / threads);
    feature_octree_pair_kernel<<<blocks, threads>>>(coord, features, indices, out, n);
}